// round 1
// baseline (speedup 1.0000x reference)
#include <cuda_runtime.h>
#include <math.h>

#define HID 512
#define DD 64
#define PHH 16
#define MAX_NOBS 50000
#define GIN_K 1024   // D*PH
#define G3H 1536     // 3*HID

// ---------------- scratch (no allocation allowed -> device globals) ----------
__device__ float  g_gru_in[(size_t)MAX_NOBS * GIN_K];  // [NOBS, 1024]
__device__ float  g_hg    [(size_t)MAX_NOBS * HID];    // gathered h rows
__device__ float  g_gi    [(size_t)MAX_NOBS * G3H];    // gru_in @ Wih^T
__device__ float  g_gh    [(size_t)MAX_NOBS * G3H];    // h_g    @ Whh^T
__device__ double g_loss;

// ---------------- prep: loss + feats @ w_prep + h gather ---------------------
__global__ void prep_kernel(const float* __restrict__ h,
                            const float* __restrict__ p,
                            const float* __restrict__ X,
                            const float* __restrict__ Mm,
                            const int*   __restrict__ i_obs,
                            const float* __restrict__ w_prep,   // [D,4,PH]
                            const float* __restrict__ b_prep,   // [D,PH]
                            float* __restrict__ gru_in,
                            float* __restrict__ hg,
                            double* __restrict__ loss_acc,
                            int nobs)
{
    __shared__ float w_s[DD * 4 * PHH];   // 4096
    __shared__ float b_s[DD * PHH];       // 1024
    __shared__ float f_s[DD * 4];
    __shared__ float m_s[DD];
    __shared__ double red[128];

    const int tid = threadIdx.x;
    for (int i = tid; i < DD * 4 * PHH; i += 128) w_s[i] = w_prep[i];
    for (int i = tid; i < DD * PHH;     i += 128) b_s[i] = b_prep[i];

    double lsum = 0.0;
    const int j0 = blockIdx.x * 8;

    for (int r = 0; r < 8; r++) {
        const int j = j0 + r;
        if (j >= nobs) break;
        const int row = i_obs[j];

        __syncthreads();   // previous iteration's readers of f_s/m_s are done
        if (tid < DD) {
            const int d = tid;
            float x    = X [(size_t)j * DD + d];
            float mask = Mm[(size_t)j * DD + d];
            float mean = p[(size_t)row * (2 * DD) + d];
            float v    = fabsf(p[(size_t)row * (2 * DD) + DD + d]) + 1e-6f;
            float err  = (x - mean) / sqrtf(v);
            f_s[d * 4 + 0] = x;
            f_s[d * 4 + 1] = mean;
            f_s[d * 4 + 2] = v;
            f_s[d * 4 + 3] = err;
            m_s[d] = mask;
            lsum += 0.5 * (double)((err * err + logf(v)) * mask);
        }
        __syncthreads();

        // gather old h row (coalesced float4)
        {
            const float4* src = (const float4*)&h [(size_t)row * HID];
            float4*       dst = (float4*)      &hg[(size_t)j   * HID];
            for (int i = tid; i < HID / 4; i += 128) dst[i] = src[i];
        }

        // gru_in[j, d*PH+ph] = relu(b + sum_f f_s[d,f]*w[d,f,ph]) * mask[d]
        for (int o = tid; o < DD * PHH; o += 128) {
            const int d = o >> 4;
            float acc = b_s[o];
#pragma unroll
            for (int f = 0; f < 4; f++)
                acc += f_s[d * 4 + f] * w_s[(d * 4 + f) * PHH + (o & 15)];
            acc = fmaxf(acc, 0.0f) * m_s[d];
            gru_in[(size_t)j * GIN_K + o] = acc;
        }
    }

    red[tid] = lsum;
    __syncthreads();
    for (int s = 64; s > 0; s >>= 1) {
        if (tid < s) red[tid] += red[tid + s];
        __syncthreads();
    }
    if (tid == 0) atomicAdd(loss_acc, red[0]);
}

// ---------------- SGEMM NT: C[m,n] = sum_k A[m,k]*B[n,k] ---------------------
// A: [M,K] row-major, B: [N,K] row-major, C: [M,N] row-major.
// N % 128 == 0, K % 16 == 0; M arbitrary (edge-guarded).
__global__ __launch_bounds__(256)
void sgemm_nt(const float* __restrict__ A, const float* __restrict__ B,
              float* __restrict__ C, int M, int N, int K)
{
    const int BM = 128, BN = 128, BK = 16, TM = 8, TN = 8;
    __shared__ float As[BK][BM];
    __shared__ float Bs[BK][BN];

    const int tid = threadIdx.x;
    const int tx = tid % 16;        // -> n direction
    const int ty = tid / 16;        // -> m direction
    const int m0 = blockIdx.y * BM;
    const int n0 = blockIdx.x * BN;

    float acc[TM][TN];
#pragma unroll
    for (int i = 0; i < TM; i++)
#pragma unroll
        for (int j = 0; j < TN; j++) acc[i][j] = 0.0f;

    for (int k0 = 0; k0 < K; k0 += BK) {
        // load A tile 128x16 (2 float4 per thread), transpose into As[k][m]
#pragma unroll
        for (int i = 0; i < 2; i++) {
            const int idx = tid + i * 256;       // 0..511 float4 slots
            const int row = idx >> 2;            // 0..127
            const int kq  = idx & 3;             // 0..3
            float4 v = make_float4(0.f, 0.f, 0.f, 0.f);
            const int gm = m0 + row;
            if (gm < M) v = *(const float4*)&A[(size_t)gm * K + k0 + kq * 4];
            As[kq * 4 + 0][row] = v.x;
            As[kq * 4 + 1][row] = v.y;
            As[kq * 4 + 2][row] = v.z;
            As[kq * 4 + 3][row] = v.w;
        }
        // load B tile 128x16
#pragma unroll
        for (int i = 0; i < 2; i++) {
            const int idx = tid + i * 256;
            const int row = idx >> 2;
            const int kq  = idx & 3;
            float4 v = *(const float4*)&B[(size_t)(n0 + row) * K + k0 + kq * 4];
            Bs[kq * 4 + 0][row] = v.x;
            Bs[kq * 4 + 1][row] = v.y;
            Bs[kq * 4 + 2][row] = v.z;
            Bs[kq * 4 + 3][row] = v.w;
        }
        __syncthreads();

#pragma unroll
        for (int k = 0; k < BK; k++) {
            float a[TM], b[TN];
#pragma unroll
            for (int i = 0; i < TM; i++) a[i] = As[k][ty * TM + i];
#pragma unroll
            for (int j = 0; j < TN; j++) b[j] = Bs[k][tx * TN + j];
#pragma unroll
            for (int i = 0; i < TM; i++)
#pragma unroll
                for (int j = 0; j < TN; j++) acc[i][j] = fmaf(a[i], b[j], acc[i][j]);
        }
        __syncthreads();
    }

#pragma unroll
    for (int i = 0; i < TM; i++) {
        const int gm = m0 + ty * TM + i;
        if (gm < M) {
#pragma unroll
            for (int j = 0; j < TN; j += 4) {
                float4 v = make_float4(acc[i][j], acc[i][j + 1], acc[i][j + 2], acc[i][j + 3]);
                *(float4*)&C[(size_t)gm * N + n0 + tx * TN + j] = v;
            }
        }
    }
}

// ---------------- GRU epilogue + guarded scatter + loss store ----------------
__global__ void gru_final(const float* __restrict__ gi,
                          const float* __restrict__ gh,
                          const float* __restrict__ hg,
                          const int*   __restrict__ i_obs,
                          const float* __restrict__ bih,
                          const float* __restrict__ bhh,
                          float* __restrict__ out,
                          const double* __restrict__ loss_acc,
                          int nobs, size_t loss_idx)
{
    const long long idx = (long long)blockIdx.x * blockDim.x + threadIdx.x;
    if (idx == 0) out[loss_idx] = (float)(*loss_acc);

    const long long total = (long long)nobs * HID;
    if (idx >= total) return;
    const int j = (int)(idx >> 9);
    const int u = (int)(idx & (HID - 1));

    const size_t base = (size_t)j * G3H;
    float ir  = gi[base + u]            + bih[u];
    float hr  = gh[base + u]            + bhh[u];
    float iz  = gi[base + HID + u]      + bih[HID + u];
    float hz  = gh[base + HID + u]      + bhh[HID + u];
    float inn = gi[base + 2 * HID + u]  + bih[2 * HID + u];
    float hn  = gh[base + 2 * HID + u]  + bhh[2 * HID + u];

    float r = 1.0f / (1.0f + expf(-(ir + hr)));
    float z = 1.0f / (1.0f + expf(-(iz + hz)));
    float n = tanhf(inn + r * hn);
    float hprev = hg[(size_t)j * HID + u];
    float hnew = (1.0f - z) * n + z * hprev;

    // last-occurrence-wins scatter (i_obs sorted)
    const int my = i_obs[j];
    if (j == nobs - 1 || i_obs[j + 1] != my)
        out[(size_t)my * HID + u] = hnew;
}

// ---------------- launch ------------------------------------------------------
extern "C" void kernel_launch(void* const* d_in, const int* in_sizes, int n_in,
                              void* d_out, int out_size)
{
    const float* h      = (const float*)d_in[0];
    const float* p      = (const float*)d_in[1];
    const float* X_obs  = (const float*)d_in[2];
    const float* M_obs  = (const float*)d_in[3];
    const int*   i_obs  = (const int*)  d_in[4];
    const float* w_prep = (const float*)d_in[5];
    const float* b_prep = (const float*)d_in[6];
    const float* w_ih   = (const float*)d_in[7];
    const float* w_hh   = (const float*)d_in[8];
    const float* b_ih   = (const float*)d_in[9];
    const float* b_hh   = (const float*)d_in[10];
    float* out = (float*)d_out;

    const int nobs   = in_sizes[4];
    const size_t hsz = (size_t)in_sizes[0];      // N*HID

    float  *s_gru_in, *s_hg, *s_gi, *s_gh;
    double *s_loss;
    cudaGetSymbolAddress((void**)&s_gru_in, g_gru_in);
    cudaGetSymbolAddress((void**)&s_hg,     g_hg);
    cudaGetSymbolAddress((void**)&s_gi,     g_gi);
    cudaGetSymbolAddress((void**)&s_gh,     g_gh);
    cudaGetSymbolAddress((void**)&s_loss,   g_loss);

    // 1) h_new starts as a copy of h; zero the loss accumulator
    cudaMemcpyAsync(out, h, hsz * sizeof(float), cudaMemcpyDeviceToDevice);
    cudaMemsetAsync(s_loss, 0, sizeof(double));

    // 2) prep: loss + gru_in + h gather
    prep_kernel<<<(nobs + 7) / 8, 128>>>(h, p, X_obs, M_obs, i_obs, w_prep, b_prep,
                                         s_gru_in, s_hg, s_loss, nobs);

    // 3) gi = gru_in @ Wih^T   [nobs,1536], K=1024
    {
        dim3 grid(G3H / 128, (nobs + 127) / 128);
        sgemm_nt<<<grid, 256>>>(s_gru_in, w_ih, s_gi, nobs, G3H, GIN_K);
    }
    // 4) gh = h_g @ Whh^T      [nobs,1536], K=512
    {
        dim3 grid(G3H / 128, (nobs + 127) / 128);
        sgemm_nt<<<grid, 256>>>(s_hg, w_hh, s_gh, nobs, G3H, HID);
    }

    // 5) GRU cell + scatter + loss
    {
        long long total = (long long)nobs * HID;
        int blocks = (int)((total + 255) / 256);
        gru_final<<<blocks, 256>>>(s_gi, s_gh, s_hg, i_obs, b_ih, b_hh,
                                   out, s_loss, nobs, hsz);
    }
}

// round 3
// speedup vs baseline: 1.4501x; 1.4501x over previous
#include <cuda_runtime.h>
#include <cuda_bf16.h>
#include <math.h>
#include <stdint.h>

#define HID 512
#define DD 64
#define PHH 16
#define N3H 1536          // 3*HID
#define G1K 1024          // D*PH
#define G2K 512           // HID
#define MAX_M 50048       // 391 * 128 (padded row count)

// ---------------- scratch (device globals; no allocation allowed) -----------
__device__ __nv_bfloat16 g_a1h[(size_t)MAX_M * G1K];
__device__ __nv_bfloat16 g_a1l[(size_t)MAX_M * G1K];
__device__ __nv_bfloat16 g_a2h[(size_t)MAX_M * G2K];
__device__ __nv_bfloat16 g_a2l[(size_t)MAX_M * G2K];
__device__ __nv_bfloat16 g_w1h[(size_t)N3H * G1K];
__device__ __nv_bfloat16 g_w1l[(size_t)N3H * G1K];
__device__ __nv_bfloat16 g_w2h[(size_t)N3H * G2K];
__device__ __nv_bfloat16 g_w2l[(size_t)N3H * G2K];
__device__ float  g_hg[(size_t)MAX_M * HID];
__device__ float  g_gi[(size_t)50000 * N3H];
__device__ float  g_gh[(size_t)50000 * N3H];
__device__ double g_loss;

// ---------------- PTX helpers ------------------------------------------------
__device__ __forceinline__ uint32_t smem_u32(const void* p) {
    uint32_t a;
    asm("{ .reg .u64 t; cvta.to.shared.u64 t, %1; cvt.u32.u64 %0, t; }"
        : "=r"(a) : "l"(p));
    return a;
}
#define CP_ASYNC16(s, g) \
    asm volatile("cp.async.cg.shared.global [%0], [%1], 16;" :: "r"(s), "l"(g))
#define CP_COMMIT() asm volatile("cp.async.commit_group;" ::: "memory")
#define CP_WAIT1()  asm volatile("cp.async.wait_group 1;" ::: "memory")

__device__ __forceinline__ void ldsm_x4(uint32_t (&r)[4], uint32_t addr) {
    asm volatile("ldmatrix.sync.aligned.m8n8.x4.shared.b16 {%0,%1,%2,%3}, [%4];"
        : "=r"(r[0]), "=r"(r[1]), "=r"(r[2]), "=r"(r[3]) : "r"(addr));
}
__device__ __forceinline__ void mma16816(float (&d)[4], const uint32_t (&a)[4],
                                         const uint32_t* b) {
    asm volatile("mma.sync.aligned.m16n8k16.row.col.f32.bf16.bf16.f32 "
        "{%0,%1,%2,%3}, {%4,%5,%6,%7}, {%8,%9}, {%0,%1,%2,%3};"
        : "+f"(d[0]), "+f"(d[1]), "+f"(d[2]), "+f"(d[3])
        : "r"(a[0]), "r"(a[1]), "r"(a[2]), "r"(a[3]), "r"(b[0]), "r"(b[1]));
}

// ---------------- weight conversion to bf16 hi/lo ----------------------------
__global__ void conv_w_kernel(const float* __restrict__ w,
                              __nv_bfloat16* __restrict__ hi,
                              __nv_bfloat16* __restrict__ lo, int n)
{
    int i = blockIdx.x * blockDim.x + threadIdx.x;
    if (i >= n) return;
    float x = w[i];
    __nv_bfloat16 h = __float2bfloat16(x);
    hi[i] = h;
    lo[i] = __float2bfloat16(x - __bfloat162float(h));
}

// ---------------- prep: loss + feats @ w_prep (-> bf16 hi/lo) + h gather -----
__global__ void prep_kernel(const float* __restrict__ h,
                            const float* __restrict__ p,
                            const float* __restrict__ X,
                            const float* __restrict__ Mm,
                            const int*   __restrict__ i_obs,
                            const float* __restrict__ w_prep,
                            const float* __restrict__ b_prep,
                            __nv_bfloat16* __restrict__ a1h,
                            __nv_bfloat16* __restrict__ a1l,
                            __nv_bfloat16* __restrict__ a2h,
                            __nv_bfloat16* __restrict__ a2l,
                            float* __restrict__ hg,
                            double* __restrict__ loss_acc,
                            int nobs)
{
    __shared__ float w_s[DD * 4 * PHH];
    __shared__ float b_s[DD * PHH];
    __shared__ float f_s[DD * 4];
    __shared__ float m_s[DD];
    __shared__ double red[128];

    const int tid = threadIdx.x;
    for (int i = tid; i < DD * 4 * PHH; i += 128) w_s[i] = w_prep[i];
    for (int i = tid; i < DD * PHH;     i += 128) b_s[i] = b_prep[i];

    double lsum = 0.0;
    const int j0 = blockIdx.x * 8;

    for (int r = 0; r < 8; r++) {
        const int j = j0 + r;
        if (j >= nobs) break;
        const int row = i_obs[j];

        __syncthreads();
        if (tid < DD) {
            const int d = tid;
            float x    = X [(size_t)j * DD + d];
            float mask = Mm[(size_t)j * DD + d];
            float mean = p[(size_t)row * (2 * DD) + d];
            float v    = fabsf(p[(size_t)row * (2 * DD) + DD + d]) + 1e-6f;
            float err  = (x - mean) / sqrtf(v);
            f_s[d * 4 + 0] = x;
            f_s[d * 4 + 1] = mean;
            f_s[d * 4 + 2] = v;
            f_s[d * 4 + 3] = err;
            m_s[d] = mask;
            lsum += 0.5 * (double)((err * err + logf(v)) * mask);
        }
        __syncthreads();

        // gather old h row (f32 for epilogue) + bf16 hi/lo for GEMM2 A
        for (int i = tid; i < HID; i += 128) {
            float v = h[(size_t)row * HID + i];
            hg[(size_t)j * HID + i] = v;
            __nv_bfloat16 bh = __float2bfloat16(v);
            a2h[(size_t)j * HID + i] = bh;
            a2l[(size_t)j * HID + i] = __float2bfloat16(v - __bfloat162float(bh));
        }

        // gru_in -> bf16 hi/lo
        for (int o = tid; o < DD * PHH; o += 128) {
            const int d = o >> 4;
            float acc = b_s[o];
#pragma unroll
            for (int f = 0; f < 4; f++)
                acc += f_s[d * 4 + f] * w_s[(d * 4 + f) * PHH + (o & 15)];
            acc = fmaxf(acc, 0.0f) * m_s[d];
            __nv_bfloat16 bh = __float2bfloat16(acc);
            a1h[(size_t)j * G1K + o] = bh;
            a1l[(size_t)j * G1K + o] = __float2bfloat16(acc - __bfloat162float(bh));
        }
    }

    red[tid] = lsum;
    __syncthreads();
    for (int s = 64; s > 0; s >>= 1) {
        if (tid < s) red[tid] += red[tid + s];
        __syncthreads();
    }
    if (tid == 0) atomicAdd(loss_acc, red[0]);
}

// ---------------- HMMA bf16 split-3 GEMM NT ----------------------------------
// C[m,n] = Ahi[m,:]Bhi[n,:] + Alo[m,:]Bhi[n,:] + Ahi[m,:]Blo[n,:]
// A: [MAX_M, K] bf16 row-major, B: [N3H, K] bf16 row-major, C: [Mrows, N3H] f32.
// CTA tile 128x128, BK=32, 3-stage cp.async pipeline.
#define LDT 80                       // bytes per smem row: 32 bf16 + 8 pad
#define T_AH 0
#define T_AL (128 * LDT)             // 10240
#define T_BH (2 * 128 * LDT)
#define T_BL (3 * 128 * LDT)
#define STAGE_BYTES (4 * 128 * LDT)  // 40960
#define SM_TOTAL (3 * STAGE_BYTES)   // 122880

__global__ __launch_bounds__(256)
void gemm_mma3(const __nv_bfloat16* __restrict__ Ah,
               const __nv_bfloat16* __restrict__ Al,
               const __nv_bfloat16* __restrict__ Bh,
               const __nv_bfloat16* __restrict__ Bl,
               float* __restrict__ C, int Mrows, int K)
{
    extern __shared__ char sm[];
    const uint32_t smb = smem_u32(sm);
    const int tid  = threadIdx.x;
    const int lane = tid & 31;
    const int wid  = tid >> 5;
    const int wm   = wid & 1;        // 0..1 -> m offset 64*wm
    const int wn   = wid >> 1;       // 0..3 -> n offset 32*wn
    const int m0 = blockIdx.y * 128;
    const int n0 = blockIdx.x * 128;
    const int nkt = K >> 5;

    float acc[4][4][4];
#pragma unroll
    for (int a = 0; a < 4; a++)
#pragma unroll
        for (int b = 0; b < 4; b++)
#pragma unroll
            for (int c = 0; c < 4; c++) acc[a][b][c] = 0.0f;

    // per-thread load slots: 2 x (row, seg) covering a 128x32 tile in 16B chunks
    const int r_ld = tid >> 2;           // base row 0..63
    const int s_ld = tid & 3;            // seg 0..3

#define LOAD_TILE(kt, st) do {                                                  \
    const uint32_t sb_ = smb + (uint32_t)(st) * STAGE_BYTES;                    \
    _Pragma("unroll")                                                           \
    for (int i_ = 0; i_ < 2; i_++) {                                            \
        const int row_ = r_ld + i_ * 64;                                        \
        const size_t ga_ = (size_t)(m0 + row_) * K + ((kt) << 5) + (s_ld << 3); \
        const size_t gb_ = (size_t)(n0 + row_) * K + ((kt) << 5) + (s_ld << 3); \
        const uint32_t so_ = row_ * LDT + (s_ld << 4);                          \
        CP_ASYNC16(sb_ + T_AH + so_, Ah + ga_);                                 \
        CP_ASYNC16(sb_ + T_AL + so_, Al + ga_);                                 \
        CP_ASYNC16(sb_ + T_BH + so_, Bh + gb_);                                 \
        CP_ASYNC16(sb_ + T_BL + so_, Bl + gb_);                                 \
    } } while (0)

    LOAD_TILE(0, 0); CP_COMMIT();
    LOAD_TILE(1, 1); CP_COMMIT();

    // precomputed fragment smem offsets (within a stage)
    const uint32_t a_off = (uint32_t)((wm * 64 + (lane & 15)) * LDT + ((lane >> 4) << 4));
    const uint32_t b_off = (uint32_t)((wn * 32 + ((lane >> 4) << 3) + (lane & 7)) * LDT
                                      + (((lane >> 3) & 1) << 4));

    for (int kt = 0; kt < nkt; kt++) {
        CP_WAIT1();
        __syncthreads();
        if (kt + 2 < nkt) { LOAD_TILE(kt + 2, (kt + 2) % 3); }
        CP_COMMIT();

        const uint32_t sb = smb + (uint32_t)(kt % 3) * STAGE_BYTES;
#pragma unroll
        for (int ks = 0; ks < 2; ks++) {
            uint32_t ah[4][4], al[4][4], bh[4][2], bl[4][2];
#pragma unroll
            for (int mb = 0; mb < 4; mb++) {
                const uint32_t ra = sb + T_AH + a_off + mb * (16 * LDT) + (ks << 5);
                ldsm_x4(ah[mb], ra);
                ldsm_x4(al[mb], ra + T_AL);
            }
#pragma unroll
            for (int ng = 0; ng < 2; ng++) {
                const uint32_t rb = sb + T_BH + b_off + ng * (16 * LDT) + (ks << 5);
                uint32_t t[4];
                ldsm_x4(t, rb);
                bh[ng * 2][0] = t[0]; bh[ng * 2][1] = t[1];
                bh[ng * 2 + 1][0] = t[2]; bh[ng * 2 + 1][1] = t[3];
                ldsm_x4(t, rb + (T_BL - T_BH));
                bl[ng * 2][0] = t[0]; bl[ng * 2][1] = t[1];
                bl[ng * 2 + 1][0] = t[2]; bl[ng * 2 + 1][1] = t[3];
            }
#pragma unroll
            for (int mb = 0; mb < 4; mb++)
#pragma unroll
                for (int nb = 0; nb < 4; nb++) {
                    mma16816(acc[mb][nb], ah[mb], bh[nb]);
                    mma16816(acc[mb][nb], al[mb], bh[nb]);
                    mma16816(acc[mb][nb], ah[mb], bl[nb]);
                }
        }
    }

    // epilogue: write C
#pragma unroll
    for (int mb = 0; mb < 4; mb++) {
        const int rbase = m0 + wm * 64 + mb * 16 + (lane >> 2);
#pragma unroll
        for (int half = 0; half < 2; half++) {
            const int row = rbase + half * 8;
            if (row < Mrows) {
                float* cp = C + (size_t)row * N3H + n0 + wn * 32 + 2 * (lane & 3);
#pragma unroll
                for (int nb = 0; nb < 4; nb++) {
                    float2 v = make_float2(acc[mb][nb][half * 2],
                                           acc[mb][nb][half * 2 + 1]);
                    *(float2*)(cp + nb * 8) = v;
                }
            }
        }
    }
}

// ---------------- GRU epilogue + guarded scatter + loss store ----------------
__global__ void gru_final(const float* __restrict__ gi,
                          const float* __restrict__ gh,
                          const float* __restrict__ hg,
                          const int*   __restrict__ i_obs,
                          const float* __restrict__ bih,
                          const float* __restrict__ bhh,
                          float* __restrict__ out,
                          const double* __restrict__ loss_acc,
                          int nobs, size_t loss_idx)
{
    const long long idx = (long long)blockIdx.x * blockDim.x + threadIdx.x;
    if (idx == 0) out[loss_idx] = (float)(*loss_acc);

    const long long total = (long long)nobs * HID;
    if (idx >= total) return;
    const int j = (int)(idx >> 9);
    const int u = (int)(idx & (HID - 1));

    const size_t base = (size_t)j * N3H;
    float ir  = gi[base + u]           + bih[u];
    float hr  = gh[base + u]           + bhh[u];
    float iz  = gi[base + HID + u]     + bih[HID + u];
    float hz  = gh[base + HID + u]     + bhh[HID + u];
    float inn = gi[base + 2 * HID + u] + bih[2 * HID + u];
    float hn  = gh[base + 2 * HID + u] + bhh[2 * HID + u];

    float r = 1.0f / (1.0f + expf(-(ir + hr)));
    float z = 1.0f / (1.0f + expf(-(iz + hz)));
    float n = tanhf(inn + r * hn);
    float hprev = hg[(size_t)j * HID + u];
    float hnew = (1.0f - z) * n + z * hprev;

    const int my = i_obs[j];
    if (j == nobs - 1 || i_obs[j + 1] != my)
        out[(size_t)my * HID + u] = hnew;
}

// ---------------- launch ------------------------------------------------------
extern "C" void kernel_launch(void* const* d_in, const int* in_sizes, int n_in,
                              void* d_out, int out_size)
{
    const float* h      = (const float*)d_in[0];
    const float* p      = (const float*)d_in[1];
    const float* X_obs  = (const float*)d_in[2];
    const float* M_obs  = (const float*)d_in[3];
    const int*   i_obs  = (const int*)  d_in[4];
    const float* w_prep = (const float*)d_in[5];
    const float* b_prep = (const float*)d_in[6];
    const float* w_ih   = (const float*)d_in[7];
    const float* w_hh   = (const float*)d_in[8];
    const float* b_ih   = (const float*)d_in[9];
    const float* b_hh   = (const float*)d_in[10];
    float* out = (float*)d_out;

    const int nobs   = in_sizes[4];
    const size_t hsz = (size_t)in_sizes[0];

    __nv_bfloat16 *s_a1h, *s_a1l, *s_a2h, *s_a2l, *s_w1h, *s_w1l, *s_w2h, *s_w2l;
    float *s_hg, *s_gi, *s_gh;
    double *s_loss;
    cudaGetSymbolAddress((void**)&s_a1h, g_a1h);
    cudaGetSymbolAddress((void**)&s_a1l, g_a1l);
    cudaGetSymbolAddress((void**)&s_a2h, g_a2h);
    cudaGetSymbolAddress((void**)&s_a2l, g_a2l);
    cudaGetSymbolAddress((void**)&s_w1h, g_w1h);
    cudaGetSymbolAddress((void**)&s_w1l, g_w1l);
    cudaGetSymbolAddress((void**)&s_w2h, g_w2h);
    cudaGetSymbolAddress((void**)&s_w2l, g_w2l);
    cudaGetSymbolAddress((void**)&s_hg,  g_hg);
    cudaGetSymbolAddress((void**)&s_gi,  g_gi);
    cudaGetSymbolAddress((void**)&s_gh,  g_gh);
    cudaGetSymbolAddress((void**)&s_loss, g_loss);

    static int smem_set = 0;
    if (!smem_set) {
        cudaFuncSetAttribute(gemm_mma3, cudaFuncAttributeMaxDynamicSharedMemorySize,
                             SM_TOTAL);
        smem_set = 1;
    }

    // 1) h_new = h; loss = 0
    cudaMemcpyAsync(out, h, hsz * sizeof(float), cudaMemcpyDeviceToDevice);
    cudaMemsetAsync(s_loss, 0, sizeof(double));

    // 2) weight conversion (bf16 hi/lo)
    conv_w_kernel<<<(N3H * G1K + 255) / 256, 256>>>(w_ih, s_w1h, s_w1l, N3H * G1K);
    conv_w_kernel<<<(N3H * G2K + 255) / 256, 256>>>(w_hh, s_w2h, s_w2l, N3H * G2K);

    // 3) prep: loss + gru_in(bf16 hi/lo) + h gather
    prep_kernel<<<(nobs + 7) / 8, 128>>>(h, p, X_obs, M_obs, i_obs, w_prep, b_prep,
                                         s_a1h, s_a1l, s_a2h, s_a2l, s_hg,
                                         s_loss, nobs);

    // 4) gi = gru_in @ Wih^T (split-3), K=1024
    {
        dim3 grid(N3H / 128, (nobs + 127) / 128);
        gemm_mma3<<<grid, 256, SM_TOTAL>>>(s_a1h, s_a1l, s_w1h, s_w1l,
                                           s_gi, nobs, G1K);
    }
    // 5) gh = h_g @ Whh^T (split-3), K=512
    {
        dim3 grid(N3H / 128, (nobs + 127) / 128);
        gemm_mma3<<<grid, 256, SM_TOTAL>>>(s_a2h, s_a2l, s_w2h, s_w2l,
                                           s_gh, nobs, G2K);
    }

    // 6) GRU cell + scatter + loss
    {
        long long total = (long long)nobs * HID;
        int blocks = (int)((total + 255) / 256);
        gru_final<<<blocks, 256>>>(s_gi, s_gh, s_hg, i_obs, b_ih, b_hh,
                                   out, s_loss, nobs, hsz);
    }
}

// round 5
// speedup vs baseline: 2.5045x; 1.7272x over previous
#include <cuda_runtime.h>
#include <cuda_bf16.h>
#include <math.h>
#include <stdint.h>

#define HID 512
#define DD 64
#define PHH 16
#define N3H 1536          // 3*HID
#define G1K 1024          // D*PH
#define G2K 512           // HID
#define MAX_M 50048       // 391 * 128 (padded row count)

// ---------------- scratch (device globals; no allocation allowed) -----------
__device__ __nv_bfloat16 g_a1h[(size_t)MAX_M * G1K];
__device__ __nv_bfloat16 g_a1l[(size_t)MAX_M * G1K];
__device__ __nv_bfloat16 g_a2h[(size_t)MAX_M * G2K];
__device__ __nv_bfloat16 g_a2l[(size_t)MAX_M * G2K];
__device__ __nv_bfloat16 g_w1h[(size_t)N3H * G1K];
__device__ __nv_bfloat16 g_w1l[(size_t)N3H * G1K];
__device__ __nv_bfloat16 g_w2h[(size_t)N3H * G2K];
__device__ __nv_bfloat16 g_w2l[(size_t)N3H * G2K];
__device__ float  g_hg[(size_t)MAX_M * HID];
__device__ float  g_gi[(size_t)50000 * N3H];
__device__ float  g_gh[(size_t)50000 * N3H];
__device__ double g_loss;

// ---------------- PTX helpers ------------------------------------------------
__device__ __forceinline__ uint32_t smem_u32(const void* p) {
    uint32_t a;
    asm("{ .reg .u64 t; cvta.to.shared.u64 t, %1; cvt.u32.u64 %0, t; }"
        : "=r"(a) : "l"(p));
    return a;
}
#define CP_ASYNC16(s, g) \
    asm volatile("cp.async.cg.shared.global [%0], [%1], 16;" :: "r"(s), "l"(g))
#define CP_COMMIT() asm volatile("cp.async.commit_group;" ::: "memory")
#define CP_WAIT1()  asm volatile("cp.async.wait_group 1;" ::: "memory")

__device__ __forceinline__ void ldsm_x4(uint32_t (&r)[4], uint32_t addr) {
    asm volatile("ldmatrix.sync.aligned.m8n8.x4.shared.b16 {%0,%1,%2,%3}, [%4];"
        : "=r"(r[0]), "=r"(r[1]), "=r"(r[2]), "=r"(r[3]) : "r"(addr));
}
__device__ __forceinline__ void mma16816(float (&d)[4], const uint32_t (&a)[4],
                                         const uint32_t* b) {
    asm volatile("mma.sync.aligned.m16n8k16.row.col.f32.bf16.bf16.f32 "
        "{%0,%1,%2,%3}, {%4,%5,%6,%7}, {%8,%9}, {%0,%1,%2,%3};"
        : "+f"(d[0]), "+f"(d[1]), "+f"(d[2]), "+f"(d[3])
        : "r"(a[0]), "r"(a[1]), "r"(a[2]), "r"(a[3]), "r"(b[0]), "r"(b[1]));
}

// ---------------- weight conversion to bf16 hi/lo ----------------------------
__global__ void conv_w_kernel(const float* __restrict__ w,
                              __nv_bfloat16* __restrict__ hi,
                              __nv_bfloat16* __restrict__ lo, int n)
{
    int i = blockIdx.x * blockDim.x + threadIdx.x;
    if (i >= n) return;
    float x = w[i];
    __nv_bfloat16 h = __float2bfloat16(x);
    hi[i] = h;
    lo[i] = __float2bfloat16(x - __bfloat162float(h));
}

// ---------------- prep: loss + feats @ w_prep (-> bf16 hi/lo) + h gather -----
__global__ void prep_kernel(const float* __restrict__ h,
                            const float* __restrict__ p,
                            const float* __restrict__ X,
                            const float* __restrict__ Mm,
                            const int*   __restrict__ i_obs,
                            const float* __restrict__ w_prep,
                            const float* __restrict__ b_prep,
                            __nv_bfloat16* __restrict__ a1h,
                            __nv_bfloat16* __restrict__ a1l,
                            __nv_bfloat16* __restrict__ a2h,
                            __nv_bfloat16* __restrict__ a2l,
                            float* __restrict__ hg,
                            double* __restrict__ loss_acc,
                            int nobs)
{
    __shared__ float w_s[DD * 4 * PHH];
    __shared__ float b_s[DD * PHH];
    __shared__ float f_s[DD * 4];
    __shared__ float m_s[DD];
    __shared__ double red[128];

    const int tid = threadIdx.x;
    for (int i = tid; i < DD * 4 * PHH; i += 128) w_s[i] = w_prep[i];
    for (int i = tid; i < DD * PHH;     i += 128) b_s[i] = b_prep[i];

    double lsum = 0.0;
    const int j0 = blockIdx.x * 8;

    for (int r = 0; r < 8; r++) {
        const int j = j0 + r;
        if (j >= nobs) break;
        const int row = i_obs[j];

        __syncthreads();
        if (tid < DD) {
            const int d = tid;
            float x    = X [(size_t)j * DD + d];
            float mask = Mm[(size_t)j * DD + d];
            float mean = p[(size_t)row * (2 * DD) + d];
            float v    = fabsf(p[(size_t)row * (2 * DD) + DD + d]) + 1e-6f;
            float err  = (x - mean) / sqrtf(v);
            f_s[d * 4 + 0] = x;
            f_s[d * 4 + 1] = mean;
            f_s[d * 4 + 2] = v;
            f_s[d * 4 + 3] = err;
            m_s[d] = mask;
            lsum += 0.5 * (double)((err * err + logf(v)) * mask);
        }
        __syncthreads();

        // gather old h row (f32 for epilogue) + bf16 hi/lo for GEMM2 A
        for (int i = tid; i < HID; i += 128) {
            float v = h[(size_t)row * HID + i];
            hg[(size_t)j * HID + i] = v;
            __nv_bfloat16 bh = __float2bfloat16(v);
            a2h[(size_t)j * HID + i] = bh;
            a2l[(size_t)j * HID + i] = __float2bfloat16(v - __bfloat162float(bh));
        }

        // gru_in -> bf16 hi/lo
        for (int o = tid; o < DD * PHH; o += 128) {
            const int d = o >> 4;
            float acc = b_s[o];
#pragma unroll
            for (int f = 0; f < 4; f++)
                acc += f_s[d * 4 + f] * w_s[(d * 4 + f) * PHH + (o & 15)];
            acc = fmaxf(acc, 0.0f) * m_s[d];
            __nv_bfloat16 bh = __float2bfloat16(acc);
            a1h[(size_t)j * G1K + o] = bh;
            a1l[(size_t)j * G1K + o] = __float2bfloat16(acc - __bfloat162float(bh));
        }
    }

    red[tid] = lsum;
    __syncthreads();
    for (int s = 64; s > 0; s >>= 1) {
        if (tid < s) red[tid] += red[tid + s];
        __syncthreads();
    }
    if (tid == 0) atomicAdd(loss_acc, red[0]);
}

// ---------------- HMMA bf16 split-3 GEMM NT ----------------------------------
// C[m,n] = Ahi[m,:]Bhi[n,:] + Alo[m,:]Bhi[n,:] + Ahi[m,:]Blo[n,:]
// CTA tile 128x128, BK=32, 2-stage cp.async double buffer, 2 CTAs/SM.
#define LDT 80                       // bytes per smem row: 32 bf16 + 8 pad
#define T_AH 0
#define T_AL (128 * LDT)             // 10240
#define T_BH (2 * 128 * LDT)
#define T_BL (3 * 128 * LDT)
#define STAGE_BYTES (4 * 128 * LDT)  // 40960
#define SM_TOTAL (2 * STAGE_BYTES)   // 81920

__global__ __launch_bounds__(256, 2)
void gemm_mma3(const __nv_bfloat16* __restrict__ Ah,
               const __nv_bfloat16* __restrict__ Al,
               const __nv_bfloat16* __restrict__ Bh,
               const __nv_bfloat16* __restrict__ Bl,
               float* __restrict__ C, int Mrows, int K)
{
    extern __shared__ char sm[];
    const uint32_t smb = smem_u32(sm);
    const int tid  = threadIdx.x;
    const int lane = tid & 31;
    const int wid  = tid >> 5;
    const int wm   = wid & 1;        // 0..1 -> m offset 64*wm
    const int wn   = wid >> 1;       // 0..3 -> n offset 32*wn
    const int m0 = blockIdx.y * 128;
    const int n0 = blockIdx.x * 128;
    const int nkt = K >> 5;

    float acc[4][4][4];
#pragma unroll
    for (int a = 0; a < 4; a++)
#pragma unroll
        for (int b = 0; b < 4; b++)
#pragma unroll
            for (int c = 0; c < 4; c++) acc[a][b][c] = 0.0f;

    // per-thread load slots: 2 x (row, seg) covering a 128x32 tile in 16B chunks
    const int r_ld = tid >> 2;           // base row 0..63
    const int s_ld = tid & 3;            // seg 0..3

#define LOAD_TILE(kt, st) do {                                                  \
    const uint32_t sb_ = smb + (uint32_t)(st) * STAGE_BYTES;                    \
    _Pragma("unroll")                                                           \
    for (int i_ = 0; i_ < 2; i_++) {                                            \
        const int row_ = r_ld + i_ * 64;                                        \
        const size_t ga_ = (size_t)(m0 + row_) * K + ((kt) << 5) + (s_ld << 3); \
        const size_t gb_ = (size_t)(n0 + row_) * K + ((kt) << 5) + (s_ld << 3); \
        const uint32_t so_ = row_ * LDT + (s_ld << 4);                          \
        CP_ASYNC16(sb_ + T_AH + so_, Ah + ga_);                                 \
        CP_ASYNC16(sb_ + T_AL + so_, Al + ga_);                                 \
        CP_ASYNC16(sb_ + T_BH + so_, Bh + gb_);                                 \
        CP_ASYNC16(sb_ + T_BL + so_, Bl + gb_);                                 \
    } } while (0)

    LOAD_TILE(0, 0); CP_COMMIT();

    // precomputed fragment smem offsets (within a stage)
    const uint32_t a_off = (uint32_t)((wm * 64 + (lane & 15)) * LDT + ((lane >> 4) << 4));
    const uint32_t b_off = (uint32_t)((wn * 32 + ((lane >> 4) << 3) + (lane & 7)) * LDT
                                      + (((lane >> 3) & 1) << 4));

    for (int kt = 0; kt < nkt; kt++) {
        if (kt + 1 < nkt) { LOAD_TILE(kt + 1, (kt + 1) & 1); }
        CP_COMMIT();
        CP_WAIT1();
        __syncthreads();

        const uint32_t sb = smb + (uint32_t)(kt & 1) * STAGE_BYTES;
#pragma unroll
        for (int ks = 0; ks < 2; ks++) {
            uint32_t ah[4][4], al[4][4], bh[4][2], bl[4][2];
#pragma unroll
            for (int mb = 0; mb < 4; mb++) {
                const uint32_t ra = sb + T_AH + a_off + mb * (16 * LDT) + (ks << 5);
                ldsm_x4(ah[mb], ra);
                ldsm_x4(al[mb], ra + T_AL);
            }
#pragma unroll
            for (int ng = 0; ng < 2; ng++) {
                const uint32_t rb = sb + T_BH + b_off + ng * (16 * LDT) + (ks << 5);
                uint32_t t[4];
                ldsm_x4(t, rb);
                bh[ng * 2][0] = t[0]; bh[ng * 2][1] = t[1];
                bh[ng * 2 + 1][0] = t[2]; bh[ng * 2 + 1][1] = t[3];
                ldsm_x4(t, rb + (T_BL - T_BH));
                bl[ng * 2][0] = t[0]; bl[ng * 2][1] = t[1];
                bl[ng * 2 + 1][0] = t[2]; bl[ng * 2 + 1][1] = t[3];
            }
#pragma unroll
            for (int mb = 0; mb < 4; mb++)
#pragma unroll
                for (int nb = 0; nb < 4; nb++) {
                    mma16816(acc[mb][nb], ah[mb], bh[nb]);
                    mma16816(acc[mb][nb], al[mb], bh[nb]);
                    mma16816(acc[mb][nb], ah[mb], bl[nb]);
                }
        }
        __syncthreads();   // all warps done with stage (kt&1) before it is reloaded
    }

    // epilogue: write C
#pragma unroll
    for (int mb = 0; mb < 4; mb++) {
        const int rbase = m0 + wm * 64 + mb * 16 + (lane >> 2);
#pragma unroll
        for (int half = 0; half < 2; half++) {
            const int row = rbase + half * 8;
            if (row < Mrows) {
                float* cp = C + (size_t)row * N3H + n0 + wn * 32 + 2 * (lane & 3);
#pragma unroll
                for (int nb = 0; nb < 4; nb++) {
                    float2 v = make_float2(acc[mb][nb][half * 2],
                                           acc[mb][nb][half * 2 + 1]);
                    *(float2*)(cp + nb * 8) = v;
                }
            }
        }
    }
}

// ---------------- GRU epilogue + guarded scatter + loss store ----------------
__global__ void gru_final(const float* __restrict__ gi,
                          const float* __restrict__ gh,
                          const float* __restrict__ hg,
                          const int*   __restrict__ i_obs,
                          const float* __restrict__ bih,
                          const float* __restrict__ bhh,
                          float* __restrict__ out,
                          const double* __restrict__ loss_acc,
                          int nobs, size_t loss_idx)
{
    const long long idx = (long long)blockIdx.x * blockDim.x + threadIdx.x;
    if (idx == 0) out[loss_idx] = (float)(*loss_acc);

    const long long total = (long long)nobs * HID;
    if (idx >= total) return;
    const int j = (int)(idx >> 9);
    const int u = (int)(idx & (HID - 1));

    const size_t base = (size_t)j * N3H;
    float ir  = gi[base + u]           + bih[u];
    float hr  = gh[base + u]           + bhh[u];
    float iz  = gi[base + HID + u]     + bih[HID + u];
    float hz  = gh[base + HID + u]     + bhh[HID + u];
    float inn = gi[base + 2 * HID + u] + bih[2 * HID + u];
    float hn  = gh[base + 2 * HID + u] + bhh[2 * HID + u];

    float r = 1.0f / (1.0f + expf(-(ir + hr)));
    float z = 1.0f / (1.0f + expf(-(iz + hz)));
    float n = tanhf(inn + r * hn);
    float hprev = hg[(size_t)j * HID + u];
    float hnew = (1.0f - z) * n + z * hprev;

    const int my = i_obs[j];
    if (j == nobs - 1 || i_obs[j + 1] != my)
        out[(size_t)my * HID + u] = hnew;
}

// ---------------- launch ------------------------------------------------------
extern "C" void kernel_launch(void* const* d_in, const int* in_sizes, int n_in,
                              void* d_out, int out_size)
{
    const float* h      = (const float*)d_in[0];
    const float* p      = (const float*)d_in[1];
    const float* X_obs  = (const float*)d_in[2];
    const float* M_obs  = (const float*)d_in[3];
    const int*   i_obs  = (const int*)  d_in[4];
    const float* w_prep = (const float*)d_in[5];
    const float* b_prep = (const float*)d_in[6];
    const float* w_ih   = (const float*)d_in[7];
    const float* w_hh   = (const float*)d_in[8];
    const float* b_ih   = (const float*)d_in[9];
    const float* b_hh   = (const float*)d_in[10];
    float* out = (float*)d_out;

    const int nobs   = in_sizes[4];
    const size_t hsz = (size_t)in_sizes[0];

    __nv_bfloat16 *s_a1h, *s_a1l, *s_a2h, *s_a2l, *s_w1h, *s_w1l, *s_w2h, *s_w2l;
    float *s_hg, *s_gi, *s_gh;
    double *s_loss;
    cudaGetSymbolAddress((void**)&s_a1h, g_a1h);
    cudaGetSymbolAddress((void**)&s_a1l, g_a1l);
    cudaGetSymbolAddress((void**)&s_a2h, g_a2h);
    cudaGetSymbolAddress((void**)&s_a2l, g_a2l);
    cudaGetSymbolAddress((void**)&s_w1h, g_w1h);
    cudaGetSymbolAddress((void**)&s_w1l, g_w1l);
    cudaGetSymbolAddress((void**)&s_w2h, g_w2h);
    cudaGetSymbolAddress((void**)&s_w2l, g_w2l);
    cudaGetSymbolAddress((void**)&s_hg,  g_hg);
    cudaGetSymbolAddress((void**)&s_gi,  g_gi);
    cudaGetSymbolAddress((void**)&s_gh,  g_gh);
    cudaGetSymbolAddress((void**)&s_loss, g_loss);

    static int smem_set = 0;
    if (!smem_set) {
        cudaFuncSetAttribute(gemm_mma3, cudaFuncAttributeMaxDynamicSharedMemorySize,
                             SM_TOTAL);
        smem_set = 1;
    }

    // 1) h_new = h; loss = 0
    cudaMemcpyAsync(out, h, hsz * sizeof(float), cudaMemcpyDeviceToDevice);
    cudaMemsetAsync(s_loss, 0, sizeof(double));

    // 2) weight conversion (bf16 hi/lo)
    conv_w_kernel<<<(N3H * G1K + 255) / 256, 256>>>(w_ih, s_w1h, s_w1l, N3H * G1K);
    conv_w_kernel<<<(N3H * G2K + 255) / 256, 256>>>(w_hh, s_w2h, s_w2l, N3H * G2K);

    // 3) prep: loss + gru_in(bf16 hi/lo) + h gather
    prep_kernel<<<(nobs + 7) / 8, 128>>>(h, p, X_obs, M_obs, i_obs, w_prep, b_prep,
                                         s_a1h, s_a1l, s_a2h, s_a2l, s_hg,
                                         s_loss, nobs);

    // 4) gi = gru_in @ Wih^T (split-3), K=1024
    {
        dim3 grid(N3H / 128, (nobs + 127) / 128);
        gemm_mma3<<<grid, 256, SM_TOTAL>>>(s_a1h, s_a1l, s_w1h, s_w1l,
                                           s_gi, nobs, G1K);
    }
    // 5) gh = h_g @ Whh^T (split-3), K=512
    {
        dim3 grid(N3H / 128, (nobs + 127) / 128);
        gemm_mma3<<<grid, 256, SM_TOTAL>>>(s_a2h, s_a2l, s_w2h, s_w2l,
                                           s_gh, nobs, G2K);
    }

    // 6) GRU cell + scatter + loss
    {
        long long total = (long long)nobs * HID;
        int blocks = (int)((total + 255) / 256);
        gru_final<<<blocks, 256>>>(s_gi, s_gh, s_hg, i_obs, b_ih, b_hh,
                                   out, s_loss, nobs, hsz);
    }
}

// round 7
// speedup vs baseline: 3.4338x; 1.3710x over previous
#include <cuda_runtime.h>
#include <cuda_bf16.h>
#include <math.h>
#include <stdint.h>

#define HID 512
#define DD 64
#define PHH 16
#define N3H 1536          // 3*HID
#define G1K 1024          // D*PH
#define G2K 512           // HID
#define MAX_M 50048       // 391 * 128 (padded row count)

// ---------------- scratch (device globals; no allocation allowed) -----------
__device__ __nv_bfloat16 g_a1h[(size_t)MAX_M * G1K];
__device__ __nv_bfloat16 g_a2h[(size_t)MAX_M * G2K];
__device__ __nv_bfloat16 g_w1h[(size_t)N3H * G1K];
__device__ __nv_bfloat16 g_w1l[(size_t)N3H * G1K];
__device__ __nv_bfloat16 g_w2h[(size_t)N3H * G2K];
__device__ __nv_bfloat16 g_w2l[(size_t)N3H * G2K];
__device__ float  g_hg[(size_t)MAX_M * HID];
__device__ float  g_gi[(size_t)50000 * N3H];
__device__ float  g_gh[(size_t)50000 * N3H];
__device__ double g_loss;

// ---------------- PTX helpers ------------------------------------------------
__device__ __forceinline__ uint32_t smem_u32(const void* p) {
    uint32_t a;
    asm("{ .reg .u64 t; cvta.to.shared.u64 t, %1; cvt.u32.u64 %0, t; }"
        : "=r"(a) : "l"(p));
    return a;
}
#define CP_ASYNC16(s, g) \
    asm volatile("cp.async.cg.shared.global [%0], [%1], 16;" :: "r"(s), "l"(g))
#define CP_COMMIT() asm volatile("cp.async.commit_group;" ::: "memory")
#define CP_WAIT1()  asm volatile("cp.async.wait_group 1;" ::: "memory")

__device__ __forceinline__ void ldsm_x4(uint32_t (&r)[4], uint32_t addr) {
    asm volatile("ldmatrix.sync.aligned.m8n8.x4.shared.b16 {%0,%1,%2,%3}, [%4];"
        : "=r"(r[0]), "=r"(r[1]), "=r"(r[2]), "=r"(r[3]) : "r"(addr));
}
__device__ __forceinline__ void mma16816(float (&d)[4], const uint32_t (&a)[4],
                                         const uint32_t* b) {
    asm volatile("mma.sync.aligned.m16n8k16.row.col.f32.bf16.bf16.f32 "
        "{%0,%1,%2,%3}, {%4,%5,%6,%7}, {%8,%9}, {%0,%1,%2,%3};"
        : "+f"(d[0]), "+f"(d[1]), "+f"(d[2]), "+f"(d[3])
        : "r"(a[0]), "r"(a[1]), "r"(a[2]), "r"(a[3]), "r"(b[0]), "r"(b[1]));
}

// ---------------- weight conversion to bf16 hi/lo ----------------------------
__global__ void conv_w_kernel(const float* __restrict__ w,
                              __nv_bfloat16* __restrict__ hi,
                              __nv_bfloat16* __restrict__ lo, int n)
{
    int i = blockIdx.x * blockDim.x + threadIdx.x;
    if (i >= n) return;
    float x = w[i];
    __nv_bfloat16 h = __float2bfloat16(x);
    hi[i] = h;
    lo[i] = __float2bfloat16(x - __bfloat162float(h));
}

// ---------------- prep: loss + feats @ w_prep (-> bf16 hi) + h gather --------
__global__ void prep_kernel(const float* __restrict__ h,
                            const float* __restrict__ p,
                            const float* __restrict__ X,
                            const float* __restrict__ Mm,
                            const int*   __restrict__ i_obs,
                            const float* __restrict__ w_prep,
                            const float* __restrict__ b_prep,
                            __nv_bfloat16* __restrict__ a1h,
                            __nv_bfloat16* __restrict__ a2h,
                            float* __restrict__ hg,
                            double* __restrict__ loss_acc,
                            int nobs)
{
    __shared__ float w_s[DD * 4 * PHH];
    __shared__ float b_s[DD * PHH];
    __shared__ float f_s[DD * 4];
    __shared__ float m_s[DD];
    __shared__ double red[128];

    const int tid = threadIdx.x;
    for (int i = tid; i < DD * 4 * PHH; i += 128) w_s[i] = w_prep[i];
    for (int i = tid; i < DD * PHH;     i += 128) b_s[i] = b_prep[i];

    double lsum = 0.0;
    const int j0 = blockIdx.x * 8;

    for (int r = 0; r < 8; r++) {
        const int j = j0 + r;
        if (j >= nobs) break;
        const int row = i_obs[j];

        __syncthreads();
        if (tid < DD) {
            const int d = tid;
            float x    = X [(size_t)j * DD + d];
            float mask = Mm[(size_t)j * DD + d];
            float mean = p[(size_t)row * (2 * DD) + d];
            float v    = fabsf(p[(size_t)row * (2 * DD) + DD + d]) + 1e-6f;
            float err  = (x - mean) / sqrtf(v);
            f_s[d * 4 + 0] = x;
            f_s[d * 4 + 1] = mean;
            f_s[d * 4 + 2] = v;
            f_s[d * 4 + 3] = err;
            m_s[d] = mask;
            lsum += 0.5 * (double)((err * err + logf(v)) * mask);
        }
        __syncthreads();

        // gather old h row (f32 for epilogue) + bf16 hi for GEMM2 A
        for (int i = tid; i < HID; i += 128) {
            float v = h[(size_t)row * HID + i];
            hg[(size_t)j * HID + i] = v;
            a2h[(size_t)j * HID + i] = __float2bfloat16(v);
        }

        // gru_in -> bf16 hi
        for (int o = tid; o < DD * PHH; o += 128) {
            const int d = o >> 4;
            float acc = b_s[o];
#pragma unroll
            for (int f = 0; f < 4; f++)
                acc += f_s[d * 4 + f] * w_s[(d * 4 + f) * PHH + (o & 15)];
            acc = fmaxf(acc, 0.0f) * m_s[d];
            a1h[(size_t)j * G1K + o] = __float2bfloat16(acc);
        }
    }

    red[tid] = lsum;
    __syncthreads();
    for (int s = 64; s > 0; s >>= 1) {
        if (tid < s) red[tid] += red[tid + s];
        __syncthreads();
    }
    if (tid == 0) atomicAdd(loss_acc, red[0]);
}

// ---------------- HMMA bf16 split-2 GEMM NT ----------------------------------
// C[m,n] = Ahi[m,:]Bhi[n,:] + Ahi[m,:]Blo[n,:]
// CTA tile 128x128, BK=32, 3-stage cp.async pipeline, 2 CTAs/SM.
#define LDT 80                       // bytes per smem row: 32 bf16 + 8 pad
#define T_AH 0
#define T_BH (128 * LDT)             // 10240
#define T_BL (2 * 128 * LDT)
#define STAGE_BYTES (3 * 128 * LDT)  // 30720
#define SM_TOTAL (3 * STAGE_BYTES)   // 92160

__global__ __launch_bounds__(256, 2)
void gemm_mma2(const __nv_bfloat16* __restrict__ Ah,
               const __nv_bfloat16* __restrict__ Bh,
               const __nv_bfloat16* __restrict__ Bl,
               float* __restrict__ C, int Mrows, int K)
{
    extern __shared__ char sm[];
    const uint32_t smb = smem_u32(sm);
    const int tid  = threadIdx.x;
    const int lane = tid & 31;
    const int wid  = tid >> 5;
    const int wm   = wid & 1;        // 0..1 -> m offset 64*wm
    const int wn   = wid >> 1;       // 0..3 -> n offset 32*wn
    const int m0 = blockIdx.y * 128;
    const int n0 = blockIdx.x * 128;
    const int nkt = K >> 5;

    float acc[4][4][4];
#pragma unroll
    for (int a = 0; a < 4; a++)
#pragma unroll
        for (int b = 0; b < 4; b++)
#pragma unroll
            for (int c = 0; c < 4; c++) acc[a][b][c] = 0.0f;

    // per-thread load slots: 2 x (row, seg) covering a 128x32 tile in 16B chunks
    const int r_ld = tid >> 2;           // base row 0..63
    const int s_ld = tid & 3;            // seg 0..3

#define LOAD_TILE(kt, st) do {                                                  \
    const uint32_t sb_ = smb + (uint32_t)(st) * STAGE_BYTES;                    \
    _Pragma("unroll")                                                           \
    for (int i_ = 0; i_ < 2; i_++) {                                            \
        const int row_ = r_ld + i_ * 64;                                        \
        const size_t ga_ = (size_t)(m0 + row_) * K + ((kt) << 5) + (s_ld << 3); \
        const size_t gb_ = (size_t)(n0 + row_) * K + ((kt) << 5) + (s_ld << 3); \
        const uint32_t so_ = row_ * LDT + (s_ld << 4);                          \
        CP_ASYNC16(sb_ + T_AH + so_, Ah + ga_);                                 \
        CP_ASYNC16(sb_ + T_BH + so_, Bh + gb_);                                 \
        CP_ASYNC16(sb_ + T_BL + so_, Bl + gb_);                                 \
    } } while (0)

    LOAD_TILE(0, 0); CP_COMMIT();
    LOAD_TILE(1, 1); CP_COMMIT();

    // precomputed fragment smem offsets (within a stage)
    const uint32_t a_off = (uint32_t)((wm * 64 + (lane & 15)) * LDT + ((lane >> 4) << 4));
    const uint32_t b_off = (uint32_t)((wn * 32 + ((lane >> 4) << 3) + (lane & 7)) * LDT
                                      + (((lane >> 3) & 1) << 4));

    for (int kt = 0; kt < nkt; kt++) {
        CP_WAIT1();
        __syncthreads();
        if (kt + 2 < nkt) { LOAD_TILE(kt + 2, (kt + 2) % 3); }
        CP_COMMIT();

        const uint32_t sb = smb + (uint32_t)(kt % 3) * STAGE_BYTES;
#pragma unroll
        for (int ks = 0; ks < 2; ks++) {
            uint32_t ah[4][4], bh[4][2], bl[4][2];
#pragma unroll
            for (int mb = 0; mb < 4; mb++) {
                const uint32_t ra = sb + T_AH + a_off + mb * (16 * LDT) + (ks << 5);
                ldsm_x4(ah[mb], ra);
            }
#pragma unroll
            for (int ng = 0; ng < 2; ng++) {
                const uint32_t rb = sb + T_BH + b_off + ng * (16 * LDT) + (ks << 5);
                uint32_t t[4];
                ldsm_x4(t, rb);
                bh[ng * 2][0] = t[0]; bh[ng * 2][1] = t[1];
                bh[ng * 2 + 1][0] = t[2]; bh[ng * 2 + 1][1] = t[3];
                ldsm_x4(t, rb + (T_BL - T_BH));
                bl[ng * 2][0] = t[0]; bl[ng * 2][1] = t[1];
                bl[ng * 2 + 1][0] = t[2]; bl[ng * 2 + 1][1] = t[3];
            }
#pragma unroll
            for (int mb = 0; mb < 4; mb++)
#pragma unroll
                for (int nb = 0; nb < 4; nb++) {
                    mma16816(acc[mb][nb], ah[mb], bh[nb]);
                    mma16816(acc[mb][nb], ah[mb], bl[nb]);
                }
        }
    }

    // epilogue: write C
#pragma unroll
    for (int mb = 0; mb < 4; mb++) {
        const int rbase = m0 + wm * 64 + mb * 16 + (lane >> 2);
#pragma unroll
        for (int half = 0; half < 2; half++) {
            const int row = rbase + half * 8;
            if (row < Mrows) {
                float* cp = C + (size_t)row * N3H + n0 + wn * 32 + 2 * (lane & 3);
#pragma unroll
                for (int nb = 0; nb < 4; nb++) {
                    float2 v = make_float2(acc[mb][nb][half * 2],
                                           acc[mb][nb][half * 2 + 1]);
                    *(float2*)(cp + nb * 8) = v;
                }
            }
        }
    }
}

// ---------------- GRU epilogue + guarded scatter + loss store ----------------
__global__ void gru_final(const float* __restrict__ gi,
                          const float* __restrict__ gh,
                          const float* __restrict__ hg,
                          const int*   __restrict__ i_obs,
                          const float* __restrict__ bih,
                          const float* __restrict__ bhh,
                          float* __restrict__ out,
                          const double* __restrict__ loss_acc,
                          int nobs, size_t loss_idx)
{
    const long long idx = (long long)blockIdx.x * blockDim.x + threadIdx.x;
    if (idx == 0) out[loss_idx] = (float)(*loss_acc);

    const long long total = (long long)nobs * HID;
    if (idx >= total) return;
    const int j = (int)(idx >> 9);
    const int u = (int)(idx & (HID - 1));

    const size_t base = (size_t)j * N3H;
    float ir  = gi[base + u]           + bih[u];
    float hr  = gh[base + u]           + bhh[u];
    float iz  = gi[base + HID + u]     + bih[HID + u];
    float hz  = gh[base + HID + u]     + bhh[HID + u];
    float inn = gi[base + 2 * HID + u] + bih[2 * HID + u];
    float hn  = gh[base + 2 * HID + u] + bhh[2 * HID + u];

    float r = 1.0f / (1.0f + expf(-(ir + hr)));
    float z = 1.0f / (1.0f + expf(-(iz + hz)));
    float n = tanhf(inn + r * hn);
    float hprev = hg[(size_t)j * HID + u];
    float hnew = (1.0f - z) * n + z * hprev;

    const int my = i_obs[j];
    if (j == nobs - 1 || i_obs[j + 1] != my)
        out[(size_t)my * HID + u] = hnew;
}

// ---------------- launch ------------------------------------------------------
extern "C" void kernel_launch(void* const* d_in, const int* in_sizes, int n_in,
                              void* d_out, int out_size)
{
    const float* h      = (const float*)d_in[0];
    const float* p      = (const float*)d_in[1];
    const float* X_obs  = (const float*)d_in[2];
    const float* M_obs  = (const float*)d_in[3];
    const int*   i_obs  = (const int*)  d_in[4];
    const float* w_prep = (const float*)d_in[5];
    const float* b_prep = (const float*)d_in[6];
    const float* w_ih   = (const float*)d_in[7];
    const float* w_hh   = (const float*)d_in[8];
    const float* b_ih   = (const float*)d_in[9];
    const float* b_hh   = (const float*)d_in[10];
    float* out = (float*)d_out;

    const int nobs   = in_sizes[4];
    const size_t hsz = (size_t)in_sizes[0];

    __nv_bfloat16 *s_a1h, *s_a2h, *s_w1h, *s_w1l, *s_w2h, *s_w2l;
    float *s_hg, *s_gi, *s_gh;
    double *s_loss;
    cudaGetSymbolAddress((void**)&s_a1h, g_a1h);
    cudaGetSymbolAddress((void**)&s_a2h, g_a2h);
    cudaGetSymbolAddress((void**)&s_w1h, g_w1h);
    cudaGetSymbolAddress((void**)&s_w1l, g_w1l);
    cudaGetSymbolAddress((void**)&s_w2h, g_w2h);
    cudaGetSymbolAddress((void**)&s_w2l, g_w2l);
    cudaGetSymbolAddress((void**)&s_hg,  g_hg);
    cudaGetSymbolAddress((void**)&s_gi,  g_gi);
    cudaGetSymbolAddress((void**)&s_gh,  g_gh);
    cudaGetSymbolAddress((void**)&s_loss, g_loss);

    static int smem_set = 0;
    if (!smem_set) {
        cudaFuncSetAttribute(gemm_mma2, cudaFuncAttributeMaxDynamicSharedMemorySize,
                             SM_TOTAL);
        smem_set = 1;
    }

    // 1) h_new = h; loss = 0
    cudaMemcpyAsync(out, h, hsz * sizeof(float), cudaMemcpyDeviceToDevice);
    cudaMemsetAsync(s_loss, 0, sizeof(double));

    // 2) weight conversion (bf16 hi/lo)
    conv_w_kernel<<<(N3H * G1K + 255) / 256, 256>>>(w_ih, s_w1h, s_w1l, N3H * G1K);
    conv_w_kernel<<<(N3H * G2K + 255) / 256, 256>>>(w_hh, s_w2h, s_w2l, N3H * G2K);

    // 3) prep: loss + gru_in(bf16 hi) + h gather
    prep_kernel<<<(nobs + 7) / 8, 128>>>(h, p, X_obs, M_obs, i_obs, w_prep, b_prep,
                                         s_a1h, s_a2h, s_hg, s_loss, nobs);

    // 4) gi = gru_in @ Wih^T (split-2), K=1024
    {
        dim3 grid(N3H / 128, (nobs + 127) / 128);
        gemm_mma2<<<grid, 256, SM_TOTAL>>>(s_a1h, s_w1h, s_w1l, s_gi, nobs, G1K);
    }
    // 5) gh = h_g @ Whh^T (split-2), K=512
    {
        dim3 grid(N3H / 128, (nobs + 127) / 128);
        gemm_mma2<<<grid, 256, SM_TOTAL>>>(s_a2h, s_w2h, s_w2l, s_gh, nobs, G2K);
    }

    // 6) GRU cell + scatter + loss
    {
        long long total = (long long)nobs * HID;
        int blocks = (int)((total + 255) / 256);
        gru_final<<<blocks, 256>>>(s_gi, s_gh, s_hg, i_obs, b_ih, b_hh,
                                   out, s_loss, nobs, hsz);
    }
}